// round 3
// baseline (speedup 1.0000x reference)
#include <cuda_runtime.h>
#include <cuda_bf16.h>
#include <math.h>

// DeepFM fused kernel, fp32 baseline.
// Sizes (fixed by the problem):
#define BB   16384
#define FF   26
#define VV   100000
#define DD   16
#define K1   416      // F*D
#define HH1  256
#define HH2  128
#define EPSV 1e-5f

#define BM   64       // samples per block
#define TPB  512

// Folded (BN-absorbed) weights in device globals (allocation-free scratch).
__device__ float g_W1f[K1 * HH1];
__device__ float g_W2f[HH1 * HH2];
__device__ float g_b1f[HH1];
__device__ float g_b2f[HH2];

__global__ void deepfm_fold_kernel(
    const float* __restrict__ W1, const float* __restrict__ b1,
    const float* __restrict__ g1, const float* __restrict__ be1,
    const float* __restrict__ m1, const float* __restrict__ v1,
    const float* __restrict__ W2, const float* __restrict__ b2,
    const float* __restrict__ g2, const float* __restrict__ be2,
    const float* __restrict__ m2, const float* __restrict__ v2)
{
    int i = blockIdx.x * blockDim.x + threadIdx.x;
    const int N1 = K1 * HH1;            // 106496
    const int N2 = HH1 * HH2;           // 32768
    for (int idx = i; idx < N1 + N2; idx += gridDim.x * blockDim.x) {
        if (idx < N1) {
            int j = idx & (HH1 - 1);
            float sc = g1[j] * rsqrtf(v1[j] + EPSV);
            g_W1f[idx] = W1[idx] * sc;
        } else {
            int t2 = idx - N1;
            int j = t2 & (HH2 - 1);
            float sc = g2[j] * rsqrtf(v2[j] + EPSV);
            g_W2f[t2] = W2[t2] * sc;
        }
    }
    if (i < HH1) {
        float sc = g1[i] * rsqrtf(v1[i] + EPSV);
        g_b1f[i] = be1[i] + (b1[i] - m1[i]) * sc;
    }
    if (i < HH2) {
        float sc = g2[i] * rsqrtf(v2[i] + EPSV);
        g_b2f[i] = be2[i] + (b2[i] - m2[i]) * sc;
    }
}

// Shared memory layout (floats):
//  A_s   [K1][BM]      = 416*64  = 26624   (embedding tile, K-major; reused as H2_s)
//  B_s   [8][256]      = 2048              (W chunk staging, reused for layer2)
//  H1_s  [BM][HH1]     = 64*256  = 16384
//  b1f_s 256, b2f_s 128, W3_s 128, fm_s 64
#define SM_A    0
#define SM_B    (SM_A + K1 * BM)            // 26624
#define SM_H1   (SM_B + 8 * HH1)            // 28672
#define SM_B1F  (SM_H1 + BM * HH1)          // 45056
#define SM_B2F  (SM_B1F + HH1)              // 45312
#define SM_W3   (SM_B2F + HH2)              // 45440
#define SM_FM   (SM_W3 + HH2)               // 45568
#define SM_TOT  (SM_FM + BM)                // 45632 floats = 182528 bytes

__global__ void __launch_bounds__(TPB, 1) deepfm_main_kernel(
    const int*   __restrict__ X,
    const float* __restrict__ emb1,
    const float* __restrict__ emb2,
    const float* __restrict__ W3,
    const float* __restrict__ b3,
    float*       __restrict__ out)
{
    extern __shared__ float sm[];
    float* A_s   = sm + SM_A;
    float* B_s   = sm + SM_B;
    float* H1_s  = sm + SM_H1;
    float* b1f_s = sm + SM_B1F;
    float* b2f_s = sm + SM_B2F;
    float* W3_s  = sm + SM_W3;
    float* fm_s  = sm + SM_FM;
    float* H2_s  = A_s;   // reuse (A_s dead after GEMM1)

    const int t  = threadIdx.x;
    const int m0 = blockIdx.x * BM;

    // ---- stage small vectors ----
    if (t < HH1)                  b1f_s[t]        = g_b1f[t];
    else if (t < HH1 + HH2)       b2f_s[t - HH1]  = g_b2f[t - HH1];
    else if (t < HH1 + 2 * HH2)   W3_s[t - HH1 - HH2] = W3[t - HH1 - HH2];

    // ---- gather embeddings into A_s (K-major: A_s[k][m]) ----
    for (int tk = t; tk < FF * BM; tk += TPB) {
        int m = tk & (BM - 1);
        int f = tk >> 6;
        int idx = X[(m0 + m) * FF + f];
        const float4* src = (const float4*)(emb2 + ((long)f * VV + idx) * DD);
        float4 v0 = src[0], v1 = src[1], v2 = src[2], v3 = src[3];
        int base = (f * DD) * BM + m;
        A_s[base +  0 * BM] = v0.x; A_s[base +  1 * BM] = v0.y;
        A_s[base +  2 * BM] = v0.z; A_s[base +  3 * BM] = v0.w;
        A_s[base +  4 * BM] = v1.x; A_s[base +  5 * BM] = v1.y;
        A_s[base +  6 * BM] = v1.z; A_s[base +  7 * BM] = v1.w;
        A_s[base +  8 * BM] = v2.x; A_s[base +  9 * BM] = v2.y;
        A_s[base + 10 * BM] = v2.z; A_s[base + 11 * BM] = v2.w;
        A_s[base + 12 * BM] = v3.x; A_s[base + 13 * BM] = v3.y;
        A_s[base + 14 * BM] = v3.z; A_s[base + 15 * BM] = v3.w;
    }
    __syncthreads();

    // ---- FM terms (threads 0..63, one sample each) ----
    if (t < BM) {
        int m = t;
        float fm2 = 0.f;
        #pragma unroll
        for (int d = 0; d < DD; d++) {
            float s = 0.f, ss = 0.f;
            #pragma unroll
            for (int f = 0; f < FF; f++) {
                float x = A_s[(f * DD + d) * BM + m];
                s += x; ss += x * x;
            }
            fm2 += s * s - ss;
        }
        float fm1 = 0.f;
        #pragma unroll
        for (int f = 0; f < FF; f++)
            fm1 += emb1[f * VV + X[(m0 + m) * FF + f]];
        fm_s[m] = fm1 + 0.5f * fm2;
    }
    // (no sync needed: fm_s only read after later syncs)

    // ---- GEMM1: [64 x 416] @ [416 x 256] -> relu(bn) -> H1_s ----
    const int tn = t & 31;   // n = tn*8 + j  (32*8 = 256)
    const int tm = t >> 5;   // m = tm*4 + i  (16*4 = 64)

    float c[4][8];
    #pragma unroll
    for (int i = 0; i < 4; i++)
        #pragma unroll
        for (int j = 0; j < 8; j++) c[i][j] = 0.f;

    for (int k0 = 0; k0 < K1; k0 += 8) {
        __syncthreads();
        // stage 8x256 chunk of W1f (contiguous): 2048 floats, float4/thread
        *(float4*)(B_s + t * 4) = *(const float4*)(g_W1f + k0 * HH1 + t * 4);
        __syncthreads();
        #pragma unroll
        for (int kk = 0; kk < 8; kk++) {
            float a[4];
            #pragma unroll
            for (int i = 0; i < 4; i++)
                a[i] = A_s[(k0 + kk) * BM + tm * 4 + i];
            float4 bA = *(const float4*)(B_s + kk * HH1 + tn * 8);
            float4 bB = *(const float4*)(B_s + kk * HH1 + tn * 8 + 4);
            float b[8] = {bA.x, bA.y, bA.z, bA.w, bB.x, bB.y, bB.z, bB.w};
            #pragma unroll
            for (int i = 0; i < 4; i++)
                #pragma unroll
                for (int j = 0; j < 8; j++)
                    c[i][j] = fmaf(a[i], b[j], c[i][j]);
        }
    }
    __syncthreads();
    #pragma unroll
    for (int i = 0; i < 4; i++) {
        int m = tm * 4 + i;
        float4 o0, o1;
        o0.x = fmaxf(c[i][0] + b1f_s[tn * 8 + 0], 0.f);
        o0.y = fmaxf(c[i][1] + b1f_s[tn * 8 + 1], 0.f);
        o0.z = fmaxf(c[i][2] + b1f_s[tn * 8 + 2], 0.f);
        o0.w = fmaxf(c[i][3] + b1f_s[tn * 8 + 3], 0.f);
        o1.x = fmaxf(c[i][4] + b1f_s[tn * 8 + 4], 0.f);
        o1.y = fmaxf(c[i][5] + b1f_s[tn * 8 + 5], 0.f);
        o1.z = fmaxf(c[i][6] + b1f_s[tn * 8 + 6], 0.f);
        o1.w = fmaxf(c[i][7] + b1f_s[tn * 8 + 7], 0.f);
        *(float4*)(H1_s + m * HH1 + tn * 8)     = o0;
        *(float4*)(H1_s + m * HH1 + tn * 8 + 4) = o1;
    }
    __syncthreads();

    // ---- GEMM2: [64 x 256] @ [256 x 128] -> relu(bn) -> H2_s ----
    // n = tn*4 + j (32*4 = 128), m = tm*4 + i (same tm as above)
    float c2[4][4];
    #pragma unroll
    for (int i = 0; i < 4; i++)
        #pragma unroll
        for (int j = 0; j < 4; j++) c2[i][j] = 0.f;

    for (int k0 = 0; k0 < HH1; k0 += 8) {
        __syncthreads();
        // stage 8x128 chunk of W2f (contiguous): 1024 floats, float2/thread
        *(float2*)(B_s + t * 2) = *(const float2*)(g_W2f + k0 * HH2 + t * 2);
        __syncthreads();
        #pragma unroll
        for (int kk = 0; kk < 8; kk++) {
            float a[4];
            #pragma unroll
            for (int i = 0; i < 4; i++)
                a[i] = H1_s[(tm * 4 + i) * HH1 + k0 + kk];
            float4 bb = *(const float4*)(B_s + kk * HH2 + tn * 4);
            float b[4] = {bb.x, bb.y, bb.z, bb.w};
            #pragma unroll
            for (int i = 0; i < 4; i++)
                #pragma unroll
                for (int j = 0; j < 4; j++)
                    c2[i][j] = fmaf(a[i], b[j], c2[i][j]);
        }
    }
    __syncthreads();   // all reads of A_s / B_s done before H2_s (=A_s) overwrite
    #pragma unroll
    for (int i = 0; i < 4; i++) {
        int m = tm * 4 + i;
        float4 o;
        o.x = fmaxf(c2[i][0] + b2f_s[tn * 4 + 0], 0.f);
        o.y = fmaxf(c2[i][1] + b2f_s[tn * 4 + 1], 0.f);
        o.z = fmaxf(c2[i][2] + b2f_s[tn * 4 + 2], 0.f);
        o.w = fmaxf(c2[i][3] + b2f_s[tn * 4 + 3], 0.f);
        *(float4*)(H2_s + m * HH2 + tn * 4) = o;
    }
    __syncthreads();

    // ---- final: logit = H2 . W3 + b3 + fm ; sigmoid ----
    if (t < BM) {
        float acc = 0.f;
        #pragma unroll
        for (int nn = 0; nn < HH2; nn++) {
            int n = (nn + t) & (HH2 - 1);   // rotate to avoid bank conflicts
            acc += H2_s[t * HH2 + n] * W3_s[n];
        }
        float logit = acc + b3[0] + fm_s[t];
        out[m0 + t] = 1.0f / (1.0f + expf(-logit));
    }
}

extern "C" void kernel_launch(void* const* d_in, const int* in_sizes, int n_in,
                              void* d_out, int out_size)
{
    const int*   X    = (const int*)  d_in[0];
    const float* emb1 = (const float*)d_in[1];
    const float* emb2 = (const float*)d_in[2];
    const float* W1   = (const float*)d_in[3];
    const float* b1   = (const float*)d_in[4];
    const float* g1   = (const float*)d_in[5];
    const float* be1  = (const float*)d_in[6];
    const float* m1   = (const float*)d_in[7];
    const float* v1   = (const float*)d_in[8];
    const float* W2   = (const float*)d_in[9];
    const float* b2   = (const float*)d_in[10];
    const float* g2   = (const float*)d_in[11];
    const float* be2  = (const float*)d_in[12];
    const float* m2   = (const float*)d_in[13];
    const float* v2   = (const float*)d_in[14];
    const float* W3   = (const float*)d_in[15];
    const float* b3   = (const float*)d_in[16];
    float* out = (float*)d_out;

    const int smem_bytes = SM_TOT * sizeof(float);   // 182528
    cudaFuncSetAttribute(deepfm_main_kernel,
                         cudaFuncAttributeMaxDynamicSharedMemorySize, smem_bytes);

    deepfm_fold_kernel<<<272, 512>>>(W1, b1, g1, be1, m1, v1,
                                     W2, b2, g2, be2, m2, v2);
    deepfm_main_kernel<<<BB / BM, TPB, smem_bytes>>>(X, emb1, emb2, W3, b3, out);
}

// round 7
// speedup vs baseline: 4.8349x; 4.8349x over previous
#include <cuda_runtime.h>
#include <cuda_bf16.h>
#include <math.h>
#include <stdint.h>

// DeepFM fused, bf16 tensor-core (mma.sync) version.
#define BB   16384
#define FF   26
#define VV   100000
#define DD   16
#define K1   416      // F*D
#define HH1  256
#define HH2  128
#define EPSV 1e-5f

#define BM   128      // samples per block
#define TPB  512
#define NS1  (K1/16)  // 26 k-steps GEMM1
#define NS2  (HH1/16) // 16 k-steps GEMM2

// A_s row pad: 424 bf16 = 212 words (212%32=20 -> conflict-free frag loads)
#define AW   212
// H1 row pad: 264 bf16 = 132 words (132%32=4 -> conflict-free)
#define H1W  132
// Weight stage row: 24 bf16 = 12 words (12%32 pattern conflict-free)
#define STW  12

// Folded transposed bf16 weights (device-global scratch; allocation-free).
__device__ __nv_bfloat16 g_W1t[HH1 * K1];   // [n=256][k=416]
__device__ __nv_bfloat16 g_W2t[HH2 * HH1];  // [n=128][k=256]
__device__ float g_b1f[HH1];
__device__ float g_b2f[HH2];

__global__ void deepfm_fold_kernel(
    const float* __restrict__ W1, const float* __restrict__ b1,
    const float* __restrict__ g1, const float* __restrict__ be1,
    const float* __restrict__ m1, const float* __restrict__ v1,
    const float* __restrict__ W2, const float* __restrict__ b2,
    const float* __restrict__ g2, const float* __restrict__ be2,
    const float* __restrict__ m2, const float* __restrict__ v2)
{
    int i = blockIdx.x * blockDim.x + threadIdx.x;
    const int N1 = HH1 * K1;     // 106496
    const int N2 = HH2 * HH1;    // 32768
    for (int idx = i; idx < N1 + N2; idx += gridDim.x * blockDim.x) {
        if (idx < N1) {
            int n = idx / K1, k = idx - n * K1;
            float sc = g1[n] * rsqrtf(v1[n] + EPSV);
            g_W1t[idx] = __float2bfloat16_rn(W1[k * HH1 + n] * sc);
        } else {
            int t2 = idx - N1;
            int n = t2 >> 8, k = t2 & 255;   // /256, %256
            float sc = g2[n] * rsqrtf(v2[n] + EPSV);
            g_W2t[t2] = __float2bfloat16_rn(W2[k * HH2 + n] * sc);
        }
    }
    if (i < HH1) {
        float sc = g1[i] * rsqrtf(v1[i] + EPSV);
        g_b1f[i] = be1[i] + (b1[i] - m1[i]) * sc;
    }
    if (i < HH2) {
        float sc = g2[i] * rsqrtf(v2[i] + EPSV);
        g_b2f[i] = be2[i] + (b2[i] - m2[i]) * sc;
    }
}

// smem byte offsets
#define OFF_A    0                                   // 128*424*2 = 108544
#define OFF_H1   108544                              // 128*264*2 = 67584
#define OFF_ST   (OFF_H1 + 67584)                    // 2*256*24*2 = 24576
#define OFF_B1F  (OFF_ST + 24576)                    // 1024
#define OFF_B2F  (OFF_B1F + 1024)                    // 512
#define OFF_W3   (OFF_B2F + 512)                     // 512
#define OFF_FM   (OFF_W3 + 512)                      // 512
#define OFF_LG   (OFF_FM + 512)                      // 128*2*4 = 1024
#define SMEM_BYTES (OFF_LG + 1024)                   // 204288

__device__ __forceinline__ void mma_bf16(float c[4], uint32_t a0, uint32_t a1,
                                         uint32_t a2, uint32_t a3,
                                         uint32_t b0, uint32_t b1)
{
    asm volatile(
        "mma.sync.aligned.m16n8k16.row.col.f32.bf16.bf16.f32 "
        "{%0,%1,%2,%3}, {%4,%5,%6,%7}, {%8,%9}, {%0,%1,%2,%3};"
        : "+f"(c[0]), "+f"(c[1]), "+f"(c[2]), "+f"(c[3])
        : "r"(a0), "r"(a1), "r"(a2), "r"(a3), "r"(b0), "r"(b1));
}

__global__ void __launch_bounds__(TPB, 1) deepfm_main_kernel(
    const int*   __restrict__ X,
    const float* __restrict__ emb1,
    const float* __restrict__ emb2,
    const float* __restrict__ W3,
    const float* __restrict__ b3,
    float*       __restrict__ out)
{
    extern __shared__ char smem[];
    uint32_t* Aw   = (uint32_t*)(smem + OFF_A);    // bf16x2 words, row stride AW
    uint32_t* H1w  = (uint32_t*)(smem + OFF_H1);   // row stride H1W
    uint32_t* Stw  = (uint32_t*)(smem + OFF_ST);   // 2 bufs of 256*STW words
    float* b1f_s = (float*)(smem + OFF_B1F);
    float* b2f_s = (float*)(smem + OFF_B2F);
    float* w3_s  = (float*)(smem + OFF_W3);
    float* fm_s  = (float*)(smem + OFF_FM);
    float* lg_s  = (float*)(smem + OFF_LG);

    const int t    = threadIdx.x;
    const int wid  = t >> 5;
    const int lane = t & 31;
    const int g    = lane >> 2;    // 0..7
    const int tig  = lane & 3;     // 0..3
    const int m0   = blockIdx.x * BM;

    // ---- stage small vectors ----
    if (t < HH1)                  b1f_s[t]       = g_b1f[t];
    else if (t < HH1 + HH2)       b2f_s[t - HH1] = g_b2f[t - HH1];
    else if (t < HH1 + 2 * HH2)   w3_s[t - HH1 - HH2] = W3[t - HH1 - HH2];

    // ---- gather embeddings -> bf16 A_s [m][k] (k = f*16+d) ----
    for (int r = t; r < FF * BM; r += TPB) {
        int m = r & (BM - 1);
        int f = r >> 7;
        int idx = X[(m0 + m) * FF + f];
        const float4* src = (const float4*)(emb2 + ((long)f * VV + idx) * DD);
        float4 v0 = src[0], v1 = src[1], v2 = src[2], v3 = src[3];
        uint32_t* dst = Aw + m * AW + f * 8;
        __nv_bfloat162 p;
        p = __floats2bfloat162_rn(v0.x, v0.y); dst[0] = *(uint32_t*)&p;
        p = __floats2bfloat162_rn(v0.z, v0.w); dst[1] = *(uint32_t*)&p;
        p = __floats2bfloat162_rn(v1.x, v1.y); dst[2] = *(uint32_t*)&p;
        p = __floats2bfloat162_rn(v1.z, v1.w); dst[3] = *(uint32_t*)&p;
        p = __floats2bfloat162_rn(v2.x, v2.y); dst[4] = *(uint32_t*)&p;
        p = __floats2bfloat162_rn(v2.z, v2.w); dst[5] = *(uint32_t*)&p;
        p = __floats2bfloat162_rn(v3.x, v3.y); dst[6] = *(uint32_t*)&p;
        p = __floats2bfloat162_rn(v3.z, v3.w); dst[7] = *(uint32_t*)&p;
    }
    __syncthreads();

    // ---- FM (threads 0..127, one sample each; fp32 from bf16 tile) ----
    if (t < BM) {
        float sd[DD], ssd[DD];
        #pragma unroll
        for (int d = 0; d < DD; d++) { sd[d] = 0.f; ssd[d] = 0.f; }
        const uint32_t* row = Aw + t * AW;
        #pragma unroll
        for (int f = 0; f < FF; f++) {
            #pragma unroll
            for (int w = 0; w < 8; w++) {
                uint32_t u = row[f * 8 + w];
                __nv_bfloat162 p = *(__nv_bfloat162*)&u;
                float x0 = __low2float(p), x1 = __high2float(p);
                sd[2 * w]     += x0;  ssd[2 * w]     += x0 * x0;
                sd[2 * w + 1] += x1;  ssd[2 * w + 1] += x1 * x1;
            }
        }
        float fm2 = 0.f;
        #pragma unroll
        for (int d = 0; d < DD; d++) fm2 += sd[d] * sd[d] - ssd[d];
        float fm1 = 0.f;
        #pragma unroll
        for (int f = 0; f < FF; f++)
            fm1 += emb1[f * VV + X[(m0 + t) * FF + f]];
        fm_s[t] = fm1 + 0.5f * fm2;
    }

    // =========================== GEMM1 ===========================
    // C[128x256] = A[128x416] @ W1t^T.  16 warps = 8 m-strips x 2 n-strips(128).
    {
        const int mb = (wid >> 1) * 16;
        const int nb = (wid & 1) * 128;
        float c[16][4];
        #pragma unroll
        for (int j = 0; j < 16; j++)
            #pragma unroll
            for (int q = 0; q < 4; q++) c[j][q] = 0.f;

        const int sn = t >> 1, sh = t & 1;          // stage mapping: 2 thr/row
        // stage chunk 0 -> buf 0
        {
            uint4 w = *(const uint4*)(g_W1t + sn * K1 + sh * 8);
            *(uint4*)((char*)Stw + sn * 48 + sh * 16) = w;
        }
        __syncthreads();
        uint4 pf;
        pf = *(const uint4*)(g_W1t + sn * K1 + 16 + sh * 8);   // chunk 1

        for (int ks = 0; ks < NS1; ks++) {
            const uint32_t* buf = Stw + (ks & 1) * 3072;
            const int k0w = ks * 8;
            uint32_t a0 = Aw[(mb + g)     * AW + k0w + tig];
            uint32_t a1 = Aw[(mb + g + 8) * AW + k0w + tig];
            uint32_t a2 = Aw[(mb + g)     * AW + k0w + 4 + tig];
            uint32_t a3 = Aw[(mb + g + 8) * AW + k0w + 4 + tig];
            #pragma unroll
            for (int j = 0; j < 16; j++) {
                int n = nb + j * 8 + g;
                uint32_t b0 = buf[n * STW + tig];
                uint32_t b1 = buf[n * STW + 4 + tig];
                mma_bf16(c[j], a0, a1, a2, a3, b0, b1);
            }
            if (ks + 1 < NS1)
                *(uint4*)((char*)Stw + ((ks + 1) & 1) * 12288 + sn * 48 + sh * 16) = pf;
            __syncthreads();
            if (ks + 2 < NS1)
                pf = *(const uint4*)(g_W1t + sn * K1 + (ks + 2) * 16 + sh * 8);
        }

        // epilogue: bias + relu -> bf16 H1
        #pragma unroll
        for (int j = 0; j < 16; j++) {
            int n = nb + j * 8 + tig * 2;
            float h00 = fmaxf(c[j][0] + b1f_s[n],     0.f);
            float h01 = fmaxf(c[j][1] + b1f_s[n + 1], 0.f);
            float h10 = fmaxf(c[j][2] + b1f_s[n],     0.f);
            float h11 = fmaxf(c[j][3] + b1f_s[n + 1], 0.f);
            __nv_bfloat162 plo = __floats2bfloat162_rn(h00, h01);
            __nv_bfloat162 phi = __floats2bfloat162_rn(h10, h11);
            H1w[(mb + g)     * H1W + (n >> 1)] = *(uint32_t*)&plo;
            H1w[(mb + g + 8) * H1W + (n >> 1)] = *(uint32_t*)&phi;
        }
    }
    __syncthreads();

    // =========================== GEMM2 + W3 ===========================
    // C[128x128] = H1[128x256] @ W2t^T.  16 warps = 8 m-strips x 2 n-strips(64).
    {
        const int mb = (wid >> 1) * 16;
        const int nb = (wid & 1) * 64;
        float c[8][4];
        #pragma unroll
        for (int j = 0; j < 8; j++)
            #pragma unroll
            for (int q = 0; q < 4; q++) c[j][q] = 0.f;

        const int sn = t >> 2, sq = t & 3;          // stage mapping: 4 thr/row
        {
            uint2 w = *(const uint2*)(g_W2t + sn * HH1 + sq * 4);
            *(uint2*)((char*)Stw + sn * 48 + sq * 8) = w;
        }
        __syncthreads();
        uint2 pf;
        pf = *(const uint2*)(g_W2t + sn * HH1 + 16 + sq * 4);

        for (int ks = 0; ks < NS2; ks++) {
            const uint32_t* buf = Stw + (ks & 1) * 3072;
            const int k0w = ks * 8;
            uint32_t a0 = H1w[(mb + g)     * H1W + k0w + tig];
            uint32_t a1 = H1w[(mb + g + 8) * H1W + k0w + tig];
            uint32_t a2 = H1w[(mb + g)     * H1W + k0w + 4 + tig];
            uint32_t a3 = H1w[(mb + g + 8) * H1W + k0w + 4 + tig];
            #pragma unroll
            for (int j = 0; j < 8; j++) {
                int n = nb + j * 8 + g;
                uint32_t b0 = buf[n * STW + tig];
                uint32_t b1 = buf[n * STW + 4 + tig];
                mma_bf16(c[j], a0, a1, a2, a3, b0, b1);
            }
            if (ks + 1 < NS2)
                *(uint2*)((char*)Stw + ((ks + 1) & 1) * 12288 + sn * 48 + sq * 8) = pf;
            __syncthreads();
            if (ks + 2 < NS2)
                pf = *(const uint2*)(g_W2t + sn * HH1 + (ks + 2) * 16 + sq * 4);
        }

        // epilogue: bias + relu, dot with W3, reduce over tig lanes
        float s_lo = 0.f, s_hi = 0.f;
        #pragma unroll
        for (int j = 0; j < 8; j++) {
            int n = nb + j * 8 + tig * 2;
            s_lo += fmaxf(c[j][0] + b2f_s[n],     0.f) * w3_s[n]
                  + fmaxf(c[j][1] + b2f_s[n + 1], 0.f) * w3_s[n + 1];
            s_hi += fmaxf(c[j][2] + b2f_s[n],     0.f) * w3_s[n]
                  + fmaxf(c[j][3] + b2f_s[n + 1], 0.f) * w3_s[n + 1];
        }
        s_lo += __shfl_xor_sync(0xffffffffu, s_lo, 1);
        s_lo += __shfl_xor_sync(0xffffffffu, s_lo, 2);
        s_hi += __shfl_xor_sync(0xffffffffu, s_hi, 1);
        s_hi += __shfl_xor_sync(0xffffffffu, s_hi, 2);
        if (tig == 0) {
            lg_s[(mb + g)     * 2 + (wid & 1)] = s_lo;
            lg_s[(mb + g + 8) * 2 + (wid & 1)] = s_hi;
        }
    }
    __syncthreads();

    if (t < BM) {
        float logit = lg_s[t * 2] + lg_s[t * 2 + 1] + fm_s[t] + b3[0];
        out[m0 + t] = 1.0f / (1.0f + expf(-logit));
    }
}

extern "C" void kernel_launch(void* const* d_in, const int* in_sizes, int n_in,
                              void* d_out, int out_size)
{
    const int*   X    = (const int*)  d_in[0];
    const float* emb1 = (const float*)d_in[1];
    const float* emb2 = (const float*)d_in[2];
    const float* W1   = (const float*)d_in[3];
    const float* b1   = (const float*)d_in[4];
    const float* g1   = (const float*)d_in[5];
    const float* be1  = (const float*)d_in[6];
    const float* m1   = (const float*)d_in[7];
    const float* v1   = (const float*)d_in[8];
    const float* W2   = (const float*)d_in[9];
    const float* b2   = (const float*)d_in[10];
    const float* g2   = (const float*)d_in[11];
    const float* be2  = (const float*)d_in[12];
    const float* m2   = (const float*)d_in[13];
    const float* v2   = (const float*)d_in[14];
    const float* W3   = (const float*)d_in[15];
    const float* b3   = (const float*)d_in[16];
    float* out = (float*)d_out;

    cudaFuncSetAttribute(deepfm_main_kernel,
                         cudaFuncAttributeMaxDynamicSharedMemorySize, SMEM_BYTES);

    deepfm_fold_kernel<<<272, 512>>>(W1, b1, g1, be1, m1, v1,
                                     W2, b2, g2, be2, m2, v2);
    deepfm_main_kernel<<<BB / BM, TPB, SMEM_BYTES>>>(X, emb1, emb2, W3, b3, out);
}